// round 2
// baseline (speedup 1.0000x reference)
#include <cuda_runtime.h>
#include <cuda_bf16.h>
#include <math.h>

// Problem constants (fixed by the reference)
#define NN 20000      // nodes
#define EE 320000     // edges (without self loops)
#define DIN 512
#define DH 256
#define GG 128

// ---------------- scratch (device globals; no allocs allowed) ----------------
__device__ float g_bufA[NN * DH];   // xw (layer1) / hw (layer2)
__device__ float g_bufB[NN * DH];   // h1 / h2
__device__ float g_dinv[NN];
__device__ int   g_cnt[NN];         // in-degree (E edges only)
__device__ int   g_off[NN + 1];     // CSR offsets
__device__ int   g_cur[NN];         // fill cursors
__device__ int   g_csr[EE];         // CSR src lists (by dst)
__device__ int   g_gcnt[GG];        // per-graph node counts
__device__ int   g_goff[GG + 1];    // per-graph offsets

// ---------------- small utility kernels ----------------
__global__ void k_zero(int* cnt, int* cur, int* gcnt) {
    int i = blockIdx.x * blockDim.x + threadIdx.x;
    if (i < NN) { cnt[i] = 0; cur[i] = 0; }
    if (i < GG) gcnt[i] = 0;
}

__global__ void k_count(const int* __restrict__ dst, const int* __restrict__ batch,
                        int* cnt, int* gcnt) {
    int i = blockIdx.x * blockDim.x + threadIdx.x;
    if (i < EE) atomicAdd(&cnt[dst[i]], 1);
    if (i < NN) atomicAdd(&gcnt[batch[i]], 1);
}

__global__ void k_dinv(const int* __restrict__ cnt, float* dinv) {
    int i = blockIdx.x * blockDim.x + threadIdx.x;
    if (i < NN) dinv[i] = rsqrtf((float)(cnt[i] + 1));  // +1 self loop, always > 0
}

// Single-block exclusive scan (n <= 1024*chunk). off[n] = total.
__global__ void k_scan(const int* __restrict__ cnt, int n, int* off) {
    __shared__ int part[1024];
    int tid = threadIdx.x;
    int chunk = (n + 1023) / 1024;
    int s = tid * chunk;
    int e = min(s + chunk, n);
    int sum = 0;
    for (int i = s; i < e; i++) sum += cnt[i];
    part[tid] = sum;
    __syncthreads();
    for (int d = 1; d < 1024; d <<= 1) {
        int v = (tid >= d) ? part[tid - d] : 0;
        __syncthreads();
        part[tid] += v;
        __syncthreads();
    }
    int run = (tid == 0) ? 0 : part[tid - 1];
    for (int i = s; i < e; i++) { off[i] = run; run += cnt[i]; }
    if (tid == 0) off[n] = part[1023];
}

__global__ void k_fill(const int* __restrict__ src, const int* __restrict__ dst,
                       const int* __restrict__ off, int* cur, int* csr) {
    int i = blockIdx.x * blockDim.x + threadIdx.x;
    if (i < EE) {
        int d = dst[i];
        int p = atomicAdd(&cur[d], 1);
        csr[off[d] + p] = src[i];
    }
}

// ---------------- fp32 SGEMM: C[M,N] = A[M,K] @ B[K,N] ----------------
// BM=128, BN=128, BK=8, 256 threads, 8x8 register tile per thread.
// N must be a multiple of 128 (N=256 here); K a multiple of 8; M guarded.
__global__ __launch_bounds__(256) void sgemm_k(const float* __restrict__ A,
                                               const float* __restrict__ B,
                                               float* __restrict__ C,
                                               int M, int N, int K) {
    __shared__ float As[8][128];
    __shared__ float Bs[8][128];
    const int tid = threadIdx.x;
    const int bm = blockIdx.y * 128;
    const int bn = blockIdx.x * 128;
    const int tx = (tid & 15) * 8;   // output col offset within tile
    const int ty = (tid >> 4) * 8;   // output row offset within tile
    const int arow = tid >> 1;       // 0..127
    const int acol = (tid & 1) * 4;  // 0 or 4
    const int brow = tid >> 5;       // 0..7
    const int bcol = (tid & 31) * 4; // 0..124

    float acc[8][8];
#pragma unroll
    for (int i = 0; i < 8; i++)
#pragma unroll
        for (int j = 0; j < 8; j++) acc[i][j] = 0.0f;

    const bool aval = (bm + arow) < M;
    const float* Aptr = A + (size_t)(aval ? (bm + arow) : 0) * K + acol;
    const float* Bptr = B + (size_t)brow * N + bn + bcol;

    for (int k0 = 0; k0 < K; k0 += 8) {
        float4 av = aval ? *(const float4*)(Aptr + k0) : make_float4(0.f, 0.f, 0.f, 0.f);
        float4 bv = *(const float4*)(Bptr + (size_t)k0 * N);
        As[acol + 0][arow] = av.x;
        As[acol + 1][arow] = av.y;
        As[acol + 2][arow] = av.z;
        As[acol + 3][arow] = av.w;
        *(float4*)&Bs[brow][bcol] = bv;
        __syncthreads();
#pragma unroll
        for (int kk = 0; kk < 8; kk++) {
            float a[8], b[8];
            *(float4*)(a)     = *(const float4*)&As[kk][ty];
            *(float4*)(a + 4) = *(const float4*)&As[kk][ty + 4];
            *(float4*)(b)     = *(const float4*)&Bs[kk][tx];
            *(float4*)(b + 4) = *(const float4*)&Bs[kk][tx + 4];
#pragma unroll
            for (int i = 0; i < 8; i++)
#pragma unroll
                for (int j = 0; j < 8; j++) acc[i][j] = fmaf(a[i], b[j], acc[i][j]);
        }
        __syncthreads();
    }

#pragma unroll
    for (int i = 0; i < 8; i++) {
        int row = bm + ty + i;
        if (row < M) {
            float4 v0 = make_float4(acc[i][0], acc[i][1], acc[i][2], acc[i][3]);
            float4 v1 = make_float4(acc[i][4], acc[i][5], acc[i][6], acc[i][7]);
            *(float4*)&C[(size_t)row * N + bn + tx]     = v0;
            *(float4*)&C[(size_t)row * N + bn + tx + 4] = v1;
        }
    }
}

// ---------------- GCN aggregation (gather by dst) + bias + ReLU ----------------
// out[i][j] = relu( dinv[i] * ( dinv[i]*xw[i][j] + sum_s dinv[s]*xw[s][j] ) + bias[j] )
__global__ __launch_bounds__(DH) void k_agg(const float* __restrict__ xw,
                                            const float* __restrict__ bias,
                                            const float* __restrict__ dinv,
                                            const int* __restrict__ off,
                                            const int* __restrict__ csr,
                                            float* __restrict__ out) {
    const int i = blockIdx.x;
    const int j = threadIdx.x;
    __shared__ int   s_nb[DH];
    __shared__ float s_dw[DH];
    const float di = dinv[i];
    float acc = di * xw[(size_t)i * DH + j];
    const int s0 = off[i];
    const int s1 = off[i + 1];
    for (int base = s0; base < s1; base += DH) {
        int cnt = min(DH, s1 - base);
        if (j < cnt) {
            int s = csr[base + j];
            s_nb[j] = s;
            s_dw[j] = dinv[s];
        }
        __syncthreads();
        int t = 0;
        for (; t + 4 <= cnt; t += 4) {
            // 4 independent gathers in flight (L2-resident; hide ~250cyc latency)
            float v0 = xw[(size_t)s_nb[t + 0] * DH + j];
            float v1 = xw[(size_t)s_nb[t + 1] * DH + j];
            float v2 = xw[(size_t)s_nb[t + 2] * DH + j];
            float v3 = xw[(size_t)s_nb[t + 3] * DH + j];
            acc = fmaf(s_dw[t + 0], v0, acc);
            acc = fmaf(s_dw[t + 1], v1, acc);
            acc = fmaf(s_dw[t + 2], v2, acc);
            acc = fmaf(s_dw[t + 3], v3, acc);
        }
        for (; t < cnt; t++)
            acc = fmaf(s_dw[t], xw[(size_t)s_nb[t] * DH + j], acc);
        __syncthreads();
    }
    float v = fmaf(di, acc, bias[j]);
    out[(size_t)i * DH + j] = v > 0.f ? v : 0.f;
}

// ---------------- mean pool per graph + FC, fused ----------------
__global__ __launch_bounds__(DH) void k_pool(const float* __restrict__ h,
                                             const int* __restrict__ goff,
                                             const float* __restrict__ wfc,
                                             const float* __restrict__ bfc,
                                             float* __restrict__ out) {
    const int g = blockIdx.x;
    const int j = threadIdx.x;
    const int s0 = goff[g];
    const int s1 = goff[g + 1];
    float sum = 0.f;
    for (int i = s0; i < s1; i++) sum += h[(size_t)i * DH + j];
    float cntf = (float)max(s1 - s0, 1);
    float val = (sum / cntf) * wfc[j];
    __shared__ float red[DH];
    red[j] = val;
    __syncthreads();
    for (int st = DH / 2; st > 0; st >>= 1) {
        if (j < st) red[j] += red[j + st];
        __syncthreads();
    }
    if (j == 0) out[g] = red[0] + bfc[0];
}

// ---------------- launch ----------------
extern "C" void kernel_launch(void* const* d_in, const int* in_sizes, int n_in,
                              void* d_out, int out_size) {
    const float* x     = (const float*)d_in[0];
    const int*   ei    = (const int*)d_in[1];
    const int*   batch = (const int*)d_in[2];
    const float* W1    = (const float*)d_in[3];
    const float* b1    = (const float*)d_in[4];
    const float* W2    = (const float*)d_in[5];
    const float* b2    = (const float*)d_in[6];
    const float* wfc   = (const float*)d_in[7];
    const float* bfc   = (const float*)d_in[8];
    float* out = (float*)d_out;

    const int* src = ei;       // edge_index[0]
    const int* dst = ei + EE;  // edge_index[1]

    float *bufA, *bufB, *dinv;
    int *cnt, *off, *cur, *csr, *gcnt, *goff;
    cudaGetSymbolAddress((void**)&bufA, g_bufA);
    cudaGetSymbolAddress((void**)&bufB, g_bufB);
    cudaGetSymbolAddress((void**)&dinv, g_dinv);
    cudaGetSymbolAddress((void**)&cnt,  g_cnt);
    cudaGetSymbolAddress((void**)&off,  g_off);
    cudaGetSymbolAddress((void**)&cur,  g_cur);
    cudaGetSymbolAddress((void**)&csr,  g_csr);
    cudaGetSymbolAddress((void**)&gcnt, g_gcnt);
    cudaGetSymbolAddress((void**)&goff, g_goff);

    // Graph structure
    k_zero<<<(NN + 255) / 256, 256>>>(cnt, cur, gcnt);
    k_count<<<(EE + 255) / 256, 256>>>(dst, batch, cnt, gcnt);
    k_dinv<<<(NN + 255) / 256, 256>>>(cnt, dinv);
    k_scan<<<1, 1024>>>(cnt, NN, off);
    k_scan<<<1, 1024>>>(gcnt, GG, goff);
    k_fill<<<(EE + 255) / 256, 256>>>(src, dst, off, cur, csr);

    // Layer 1: xw = x @ W1 ; h1 = relu(agg(xw) + b1)
    {
        dim3 grid(DH / 128, (NN + 127) / 128);
        sgemm_k<<<grid, 256>>>(x, W1, bufA, NN, DH, DIN);
    }
    k_agg<<<NN, DH>>>(bufA, b1, dinv, off, csr, bufB);

    // Layer 2: hw = h1 @ W2 ; h2 = relu(agg(hw) + b2)
    {
        dim3 grid(DH / 128, (NN + 127) / 128);
        sgemm_k<<<grid, 256>>>(bufB, W2, bufA, NN, DH, DH);
    }
    k_agg<<<NN, DH>>>(bufA, b2, dinv, off, csr, bufB);

    // Pool + FC
    k_pool<<<GG, DH>>>(bufB, goff, wfc, bfc, out);
}

// round 4
// speedup vs baseline: 1.3795x; 1.3795x over previous
#include <cuda_runtime.h>
#include <cuda_bf16.h>
#include <cstdint>
#include <math.h>

// Problem constants (fixed by the reference)
#define NN 20000      // nodes
#define EE 320000     // edges (without self loops)
#define DIN 512
#define DH 256
#define GG 128

// ---------------- scratch (device globals; no allocs allowed) ----------------
__device__ float g_bufA[NN * DH];   // xw (layer1) / hw (layer2)
__device__ float g_bufB[NN * DH];   // h1 / h2
__device__ float g_dinv[NN];
__device__ int   g_cnt[NN];
__device__ int   g_off[NN + 1];
__device__ int   g_cur[NN];
__device__ int   g_csr[EE];
__device__ int   g_gcnt[GG];
__device__ int   g_goff[GG + 1];
__device__ int   g_part[128];       // scan partials

// ---------------- small utility kernels ----------------
__global__ void k_zero(int* cnt, int* cur, int* gcnt) {
    int i = blockIdx.x * blockDim.x + threadIdx.x;
    if (i < NN) { cnt[i] = 0; cur[i] = 0; }
    if (i < GG) gcnt[i] = 0;
}

__global__ void k_count(const int* __restrict__ dst, const int* __restrict__ batch,
                        int* cnt, int* gcnt) {
    int i = blockIdx.x * blockDim.x + threadIdx.x;
    if (i < EE) atomicAdd(&cnt[dst[i]], 1);
    if (i < NN) atomicAdd(&gcnt[batch[i]], 1);
}

__global__ void k_dinv(const int* __restrict__ cnt, float* dinv) {
    int i = blockIdx.x * blockDim.x + threadIdx.x;
    if (i < NN) dinv[i] = rsqrtf((float)(cnt[i] + 1));  // +1 self loop
}

// Hierarchical exclusive scan over NN elements
#define SCAN_BLK 256
#define SCAN_NB  ((NN + SCAN_BLK - 1) / SCAN_BLK)   // 79
__global__ void k_scan1(const int* __restrict__ cnt, int* off, int* part) {
    __shared__ int sh[SCAN_BLK];
    int t = threadIdx.x;
    int g = blockIdx.x * SCAN_BLK + t;
    int v = (g < NN) ? cnt[g] : 0;
    sh[t] = v; __syncthreads();
    for (int d = 1; d < SCAN_BLK; d <<= 1) {
        int u = (t >= d) ? sh[t - d] : 0;
        __syncthreads(); sh[t] += u; __syncthreads();
    }
    if (g < NN) off[g] = sh[t] - v;              // exclusive within block
    if (t == SCAN_BLK - 1) part[blockIdx.x] = sh[t];
}
__global__ void k_scan2(int* part) {
    __shared__ int sh[128];
    int t = threadIdx.x;
    int v = (t < SCAN_NB) ? part[t] : 0;
    sh[t] = v; __syncthreads();
    for (int d = 1; d < 128; d <<= 1) {
        int u = (t >= d) ? sh[t - d] : 0;
        __syncthreads(); sh[t] += u; __syncthreads();
    }
    if (t < SCAN_NB) part[t] = sh[t] - v;        // exclusive
    if (t == 127) part[SCAN_NB] = sh[127];       // total
}
__global__ void k_scan3(int* off, const int* __restrict__ part) {
    int g = blockIdx.x * SCAN_BLK + threadIdx.x;
    if (g < NN) off[g] += part[blockIdx.x];
    if (g == 0) off[NN] = part[SCAN_NB];
}

// small single-block scan for GG=128
__global__ void k_scan_small(const int* __restrict__ cnt, int n, int* off) {
    __shared__ int sh[128];
    int t = threadIdx.x;
    int v = (t < n) ? cnt[t] : 0;
    sh[t] = v; __syncthreads();
    for (int d = 1; d < 128; d <<= 1) {
        int u = (t >= d) ? sh[t - d] : 0;
        __syncthreads(); sh[t] += u; __syncthreads();
    }
    if (t < n) off[t] = sh[t] - v;
    if (t == 127) off[n] = sh[127];
}

__global__ void k_fill(const int* __restrict__ src, const int* __restrict__ dst,
                       const int* __restrict__ off, int* cur, int* csr) {
    int i = blockIdx.x * blockDim.x + threadIdx.x;
    if (i < EE) {
        int d = dst[i];
        int p = atomicAdd(&cur[d], 1);
        csr[off[d] + p] = src[i];
    }
}

// ================== tf32 mma.sync GEMM (3xTF32 split, fp32-accurate) ==================
// C[M,256] = A[M,KDIM] @ W[KDIM,256]
// BM=128, BN=128, BK=32, 256 threads, warp tile 64x32 via m16n8k8.
#define SA_STRIDE 36      // (stride%32)=4 -> frag bank = 4*lr+lc, bijective
#define SB_STRIDE 136     // (stride%32)=8 -> frag bank = 8*lc+lr, bijective
#define OFF_AH 0
#define OFF_AL (128 * SA_STRIDE)
#define OFF_BH (2 * 128 * SA_STRIDE)
#define OFF_BL (2 * 128 * SA_STRIDE + 32 * SB_STRIDE)
#define GEMM_SMEM ((2 * 128 * SA_STRIDE + 2 * 32 * SB_STRIDE) * 4)

__device__ __forceinline__ uint32_t f2tf(float x) {
    uint32_t r; asm("cvt.rna.tf32.f32 %0, %1;" : "=r"(r) : "f"(x)); return r;
}
__device__ __forceinline__ void mma8(float* c, const uint32_t* a, const uint32_t* b) {
    asm volatile("mma.sync.aligned.m16n8k8.row.col.f32.tf32.tf32.f32 "
                 "{%0,%1,%2,%3}, {%4,%5,%6,%7}, {%8,%9}, {%0,%1,%2,%3};"
                 : "+f"(c[0]), "+f"(c[1]), "+f"(c[2]), "+f"(c[3])
                 : "r"(a[0]), "r"(a[1]), "r"(a[2]), "r"(a[3]), "r"(b[0]), "r"(b[1]));
}
__device__ __forceinline__ void split_store(float v, float* dh, float* dl) {
    float h = __uint_as_float(f2tf(v));
    *dh = h;
    *dl = __uint_as_float(f2tf(v - h));
}

template <int KDIM>
__global__ __launch_bounds__(256, 2) void gemm_tf32(const float* __restrict__ A,
                                                    const float* __restrict__ W,
                                                    float* __restrict__ C, int M) {
    extern __shared__ float sm[];
    float* Ah = sm + OFF_AH;
    float* Al = sm + OFF_AL;
    float* Bh = sm + OFF_BH;
    float* Bl = sm + OFF_BL;
    const int tid = threadIdx.x;
    const int wid = tid >> 5, lane = tid & 31;
    const int lr = lane >> 2, lc = lane & 3;       // groupID / threadID_in_group
    const int wm = (wid & 1) * 64;                 // warp m offset (2 rows of warps)
    const int wn = (wid >> 1) * 32;                // warp n offset (4 cols of warps)
    const int bm = blockIdx.y * 128;
    const int bn = blockIdx.x * 128;

    float acc[4][4][4];
#pragma unroll
    for (int i = 0; i < 4; i++)
#pragma unroll
        for (int j = 0; j < 4; j++) {
            acc[i][j][0] = 0.f; acc[i][j][1] = 0.f; acc[i][j][2] = 0.f; acc[i][j][3] = 0.f;
        }

    for (int k0 = 0; k0 < KDIM; k0 += 32) {
        // A tile: 128 rows x 32 k (float4 loads), split hi/lo into SMEM
#pragma unroll
        for (int q = 0; q < 4; q++) {
            int i = tid + q * 256;                 // 0..1023
            int r = i >> 3, c4 = (i & 7) << 2;
            float4 v = make_float4(0.f, 0.f, 0.f, 0.f);
            if (bm + r < M) v = *(const float4*)(A + (size_t)(bm + r) * KDIM + k0 + c4);
            float* dh = Ah + r * SA_STRIDE + c4;
            float* dl = Al + r * SA_STRIDE + c4;
            split_store(v.x, dh + 0, dl + 0);
            split_store(v.y, dh + 1, dl + 1);
            split_store(v.z, dh + 2, dl + 2);
            split_store(v.w, dh + 3, dl + 3);
        }
        // B tile: 32 k-rows x 128 n (direct from W[K,256])
#pragma unroll
        for (int q = 0; q < 4; q++) {
            int i = tid + q * 256;                 // 0..1023
            int r = i >> 5, c4 = (i & 31) << 2;
            float4 v = *(const float4*)(W + (size_t)(k0 + r) * 256 + bn + c4);
            float* dh = Bh + r * SB_STRIDE + c4;
            float* dl = Bl + r * SB_STRIDE + c4;
            split_store(v.x, dh + 0, dl + 0);
            split_store(v.y, dh + 1, dl + 1);
            split_store(v.z, dh + 2, dl + 2);
            split_store(v.w, dh + 3, dl + 3);
        }
        __syncthreads();
#pragma unroll
        for (int kk = 0; kk < 32; kk += 8) {
            uint32_t ah[4][4], al[4][4];
#pragma unroll
            for (int i = 0; i < 4; i++) {
                const float* p  = Ah + (wm + i * 16 + lr) * SA_STRIDE + kk + lc;
                const float* pl = Al + (wm + i * 16 + lr) * SA_STRIDE + kk + lc;
                ah[i][0] = __float_as_uint(p[0]);
                ah[i][1] = __float_as_uint(p[8 * SA_STRIDE]);
                ah[i][2] = __float_as_uint(p[4]);
                ah[i][3] = __float_as_uint(p[8 * SA_STRIDE + 4]);
                al[i][0] = __float_as_uint(pl[0]);
                al[i][1] = __float_as_uint(pl[8 * SA_STRIDE]);
                al[i][2] = __float_as_uint(pl[4]);
                al[i][3] = __float_as_uint(pl[8 * SA_STRIDE + 4]);
            }
#pragma unroll
            for (int j = 0; j < 4; j++) {
                const float* p  = Bh + (kk + lc) * SB_STRIDE + wn + j * 8 + lr;
                const float* pl = Bl + (kk + lc) * SB_STRIDE + wn + j * 8 + lr;
                uint32_t bh[2] = { __float_as_uint(p[0]),  __float_as_uint(p[4 * SB_STRIDE]) };
                uint32_t bl[2] = { __float_as_uint(pl[0]), __float_as_uint(pl[4 * SB_STRIDE]) };
#pragma unroll
                for (int i = 0; i < 4; i++) {
                    mma8(acc[i][j], ah[i], bh);
                    mma8(acc[i][j], ah[i], bl);
                    mma8(acc[i][j], al[i], bh);
                }
            }
        }
        __syncthreads();
    }
    // epilogue
#pragma unroll
    for (int i = 0; i < 4; i++) {
        int r0 = bm + wm + i * 16 + lr;
#pragma unroll
        for (int j = 0; j < 4; j++) {
            int col = bn + wn + j * 8 + lc * 2;
            if (r0 < M) {
                float2 v = make_float2(acc[i][j][0], acc[i][j][1]);
                *(float2*)(C + (size_t)r0 * 256 + col) = v;
            }
            if (r0 + 8 < M) {
                float2 v = make_float2(acc[i][j][2], acc[i][j][3]);
                *(float2*)(C + (size_t)(r0 + 8) * 256 + col) = v;
            }
        }
    }
}

// ---------------- GCN aggregation (gather by dst) + bias + ReLU ----------------
__global__ __launch_bounds__(DH) void k_agg(const float* __restrict__ xw,
                                            const float* __restrict__ bias,
                                            const float* __restrict__ dinv,
                                            const int* __restrict__ off,
                                            const int* __restrict__ csr,
                                            float* __restrict__ out) {
    const int i = blockIdx.x;
    const int j = threadIdx.x;
    __shared__ int   s_nb[DH];
    __shared__ float s_dw[DH];
    const float di = dinv[i];
    float acc = di * xw[(size_t)i * DH + j];
    const int s0 = off[i];
    const int s1 = off[i + 1];
    for (int base = s0; base < s1; base += DH) {
        int cnt = min(DH, s1 - base);
        if (j < cnt) {
            int s = csr[base + j];
            s_nb[j] = s;
            s_dw[j] = dinv[s];
        }
        __syncthreads();
        int t = 0;
        for (; t + 4 <= cnt; t += 4) {
            float v0 = xw[(size_t)s_nb[t + 0] * DH + j];
            float v1 = xw[(size_t)s_nb[t + 1] * DH + j];
            float v2 = xw[(size_t)s_nb[t + 2] * DH + j];
            float v3 = xw[(size_t)s_nb[t + 3] * DH + j];
            acc = fmaf(s_dw[t + 0], v0, acc);
            acc = fmaf(s_dw[t + 1], v1, acc);
            acc = fmaf(s_dw[t + 2], v2, acc);
            acc = fmaf(s_dw[t + 3], v3, acc);
        }
        for (; t < cnt; t++)
            acc = fmaf(s_dw[t], xw[(size_t)s_nb[t] * DH + j], acc);
        __syncthreads();
    }
    float v = fmaf(di, acc, bias[j]);
    out[(size_t)i * DH + j] = v > 0.f ? v : 0.f;
}

// ---------------- mean pool per graph + FC, fused ----------------
__global__ __launch_bounds__(DH) void k_pool(const float* __restrict__ h,
                                             const int* __restrict__ goff,
                                             const float* __restrict__ wfc,
                                             const float* __restrict__ bfc,
                                             float* __restrict__ out) {
    const int g = blockIdx.x;
    const int j = threadIdx.x;
    const int s0 = goff[g];
    const int s1 = goff[g + 1];
    float sum = 0.f;
    for (int i = s0; i < s1; i++) sum += h[(size_t)i * DH + j];
    float cntf = (float)max(s1 - s0, 1);
    float val = (sum / cntf) * wfc[j];
    __shared__ float red[DH];
    red[j] = val;
    __syncthreads();
    for (int st = DH / 2; st > 0; st >>= 1) {
        if (j < st) red[j] += red[j + st];
        __syncthreads();
    }
    if (j == 0) out[g] = red[0] + bfc[0];
}

// ---------------- launch ----------------
extern "C" void kernel_launch(void* const* d_in, const int* in_sizes, int n_in,
                              void* d_out, int out_size) {
    const float* x     = (const float*)d_in[0];
    const int*   ei    = (const int*)d_in[1];
    const int*   batch = (const int*)d_in[2];
    const float* W1    = (const float*)d_in[3];
    const float* b1    = (const float*)d_in[4];
    const float* W2    = (const float*)d_in[5];
    const float* b2    = (const float*)d_in[6];
    const float* wfc   = (const float*)d_in[7];
    const float* bfc   = (const float*)d_in[8];
    float* out = (float*)d_out;

    const int* src = ei;       // edge_index[0]
    const int* dst = ei + EE;  // edge_index[1]

    float *bufA, *bufB, *dinv;
    int *cnt, *off, *cur, *csr, *gcnt, *goff, *part;
    cudaGetSymbolAddress((void**)&bufA, g_bufA);
    cudaGetSymbolAddress((void**)&bufB, g_bufB);
    cudaGetSymbolAddress((void**)&dinv, g_dinv);
    cudaGetSymbolAddress((void**)&cnt,  g_cnt);
    cudaGetSymbolAddress((void**)&off,  g_off);
    cudaGetSymbolAddress((void**)&cur,  g_cur);
    cudaGetSymbolAddress((void**)&csr,  g_csr);
    cudaGetSymbolAddress((void**)&gcnt, g_gcnt);
    cudaGetSymbolAddress((void**)&goff, g_goff);
    cudaGetSymbolAddress((void**)&part, g_part);

    cudaFuncSetAttribute(gemm_tf32<DIN>, cudaFuncAttributeMaxDynamicSharedMemorySize, GEMM_SMEM);
    cudaFuncSetAttribute(gemm_tf32<DH>,  cudaFuncAttributeMaxDynamicSharedMemorySize, GEMM_SMEM);

    // Graph structure
    k_zero<<<(NN + 255) / 256, 256>>>(cnt, cur, gcnt);
    k_count<<<(EE + 255) / 256, 256>>>(dst, batch, cnt, gcnt);
    k_dinv<<<(NN + 255) / 256, 256>>>(cnt, dinv);
    k_scan1<<<SCAN_NB, SCAN_BLK>>>(cnt, off, part);
    k_scan2<<<1, 128>>>(part);
    k_scan3<<<SCAN_NB, SCAN_BLK>>>(off, part);
    k_scan_small<<<1, 128>>>(gcnt, GG, goff);
    k_fill<<<(EE + 255) / 256, 256>>>(src, dst, off, cur, csr);

    dim3 ggrid(2, (NN + 127) / 128);   // (N/128, ceil(M/128))

    // Layer 1: xw = x @ W1 ; h1 = relu(agg(xw) + b1)
    gemm_tf32<DIN><<<ggrid, 256, GEMM_SMEM>>>(x, W1, bufA, NN);
    k_agg<<<NN, DH>>>(bufA, b1, dinv, off, csr, bufB);

    // Layer 2: hw = h1 @ W2 ; h2 = relu(agg(hw) + b2)
    gemm_tf32<DH><<<ggrid, 256, GEMM_SMEM>>>(bufB, W2, bufA, NN);
    k_agg<<<NN, DH>>>(bufA, b2, dinv, off, csr, bufB);

    // Pool + FC
    k_pool<<<GG, DH>>>(bufB, goff, wfc, bfc, out);
}